// round 17
// baseline (speedup 1.0000x reference)
#include <cuda_runtime.h>
#include <cstdint>

// ---------------------------------------------------------------------------
// SimpleSRNN R14: two CTAs per batch (128 srnn CTAs on distinct SMs), each
// owning 512 hidden columns (2 per thread, 8B weight-row slices) -> halves
// per-SM L1 wavefront load. Spike masks exchanged per step via global memory
// (STG + fence + atomic flag / spin + __ldcg). Accumulation order per column
// identical to the R8 passing kernel (bit-exact trajectory).
// ---------------------------------------------------------------------------

#define BETA 0.9f
#define THRESH 1.0f

static constexpr int B = 64;
static constexpr int T = 512;
static constexpr int DIN = 512;
static constexpr int H = 1024;
static constexpr int DOUT = 256;
static constexpr int ZROW = H;
static constexpr int HC = H / 2;       // columns per CTA (512)

__device__ float g_Xa[(size_t)B * T * H];
__device__ float g_WT_h1[H * H + H];
__device__ float g_WT_12[H * H + H];
__device__ float g_WT_h2[H * H + H];
__device__ float g_WT_in[DIN * H];
__device__ float g_WT_out[H * DOUT + DOUT];
__device__ int   g_flag[B][4];             // gemm tiles done per (b, tblock)
__device__ unsigned g_masks[B][2][2][16];  // [b][layer][rank][word]
__device__ int   g_xf[B][2][2];            // step counters [b][layer][rank]
__device__ float4 g_part[B][128];          // CTA1 readout partials
__device__ int   g_rflag[B];

// ---------------------------------------------------------------------------
__global__ void prep_kernel(const float* __restrict__ W_in,
                            const float* __restrict__ W_h1,
                            const float* __restrict__ W_12,
                            const float* __restrict__ W_h2,
                            const float* __restrict__ W_out) {
    const int stride = gridDim.x * blockDim.x;
    const int g = blockIdx.x * blockDim.x + threadIdx.x;

    if (g < B * 4) ((int*)g_flag)[g] = 0;
    if (g < B * 4) ((int*)g_xf)[g] = 0;
    if (g < B) g_rflag[g] = 0;

    for (int d = g; d < DIN * H; d += stride) {
        int k = d >> 10, i = d & (H - 1);
        g_WT_in[d] = W_in[i * DIN + k];
    }
    for (int d = g; d < H * H; d += stride) {
        int j = d >> 10, i = d & (H - 1);
        g_WT_h1[d] = W_h1[i * H + j];
    }
    for (int d = g; d < H * H; d += stride) {
        int j = d >> 10, i = d & (H - 1);
        g_WT_12[d] = W_12[i * H + j];
    }
    for (int d = g; d < H * H; d += stride) {
        int j = d >> 10, i = d & (H - 1);
        g_WT_h2[d] = W_h2[i * H + j];
    }
    for (int d = g; d < H * DOUT; d += stride) {
        int j = d >> 8, o = d & (DOUT - 1);
        g_WT_out[d] = W_out[o * H + j];
    }
    if (g < H) {
        g_WT_h1[H * H + g] = 0.0f;
        g_WT_12[H * H + g] = 0.0f;
        g_WT_h2[H * H + g] = 0.0f;
    }
    if (g < DOUT) g_WT_out[H * DOUT + g] = 0.0f;
}

// ---------------------------------------------------------------------------
// GEMM body (bit-exact vs R5)
// ---------------------------------------------------------------------------
#define GN H
#define GK DIN
#define BMT 128
#define BNT 64
#define BKT 16
#define NTILES (GN / BNT)

__device__ void gemm_body(const float* __restrict__ x,
                          const float* __restrict__ b_in, int gidx) {
    __shared__ float As[2][BKT][BMT + 4];
    __shared__ float Bs[2][BKT][BNT];

    const int bx = gidx & (NTILES - 1);
    const int byr = gidx >> 4;
    const int tb = byr >> 6;
    const int bb = byr & 63;
    const int bm = bb * T + tb * BMT;
    const int bn = bx * BNT;
    const int tid = threadIdx.x;
    const int tx = tid & 15;
    const int ty = tid >> 4;

    float acc[8][4];
#pragma unroll
    for (int i = 0; i < 8; ++i)
#pragma unroll
        for (int j = 0; j < 4; ++j) acc[i][j] = 0.0f;

    const int a_row0 = tid >> 2;
    const int a_kc = (tid & 3) * 4;
    const int b_k = tid >> 4;
    const int b_c = (tid & 15) * 4;

    const float* Aptr = x + (size_t)(bm + a_row0) * GK + a_kc;
    const float* Bptr = g_WT_in + (size_t)b_k * GN + bn + b_c;

    float4 pa0 = *(const float4*)(Aptr);
    float4 pa1 = *(const float4*)(Aptr + 64 * GK);
    float4 pb = *(const float4*)(Bptr);

    As[0][a_kc + 0][a_row0] = pa0.x;
    As[0][a_kc + 1][a_row0] = pa0.y;
    As[0][a_kc + 2][a_row0] = pa0.z;
    As[0][a_kc + 3][a_row0] = pa0.w;
    As[0][a_kc + 0][a_row0 + 64] = pa1.x;
    As[0][a_kc + 1][a_row0 + 64] = pa1.y;
    As[0][a_kc + 2][a_row0 + 64] = pa1.z;
    As[0][a_kc + 3][a_row0 + 64] = pa1.w;
    *(float4*)&Bs[0][b_k][b_c] = pb;
    __syncthreads();

    const int KT = GK / BKT;
    int buf = 0;
    for (int kt = 0; kt < KT; ++kt) {
        if (kt + 1 < KT) {
            const float* Ap = Aptr + (kt + 1) * BKT;
            pa0 = *(const float4*)(Ap);
            pa1 = *(const float4*)(Ap + 64 * GK);
            pb = *(const float4*)(Bptr + (size_t)(kt + 1) * BKT * GN);
        }
#pragma unroll
        for (int k = 0; k < BKT; ++k) {
            float4 a0 = *(const float4*)&As[buf][k][ty * 8];
            float4 a1 = *(const float4*)&As[buf][k][ty * 8 + 4];
            float4 bb2 = *(const float4*)&Bs[buf][k][tx * 4];
            float am[8] = {a0.x, a0.y, a0.z, a0.w, a1.x, a1.y, a1.z, a1.w};
            float bv[4] = {bb2.x, bb2.y, bb2.z, bb2.w};
#pragma unroll
            for (int i = 0; i < 8; ++i)
#pragma unroll
                for (int j = 0; j < 4; ++j)
                    acc[i][j] = fmaf(am[i], bv[j], acc[i][j]);
        }
        if (kt + 1 < KT) {
            const int nb = buf ^ 1;
            As[nb][a_kc + 0][a_row0] = pa0.x;
            As[nb][a_kc + 1][a_row0] = pa0.y;
            As[nb][a_kc + 2][a_row0] = pa0.z;
            As[nb][a_kc + 3][a_row0] = pa0.w;
            As[nb][a_kc + 0][a_row0 + 64] = pa1.x;
            As[nb][a_kc + 1][a_row0 + 64] = pa1.y;
            As[nb][a_kc + 2][a_row0 + 64] = pa1.z;
            As[nb][a_kc + 3][a_row0 + 64] = pa1.w;
            *(float4*)&Bs[nb][b_k][b_c] = pb;
        }
        buf ^= 1;
        __syncthreads();
    }

    float bias[4];
#pragma unroll
    for (int j = 0; j < 4; ++j) bias[j] = b_in[bn + tx * 4 + j];
#pragma unroll
    for (int i = 0; i < 8; ++i) {
        float4 o;
        o.x = acc[i][0] + bias[0];
        o.y = acc[i][1] + bias[1];
        o.z = acc[i][2] + bias[2];
        o.w = acc[i][3] + bias[3];
        *(float4*)&g_Xa[(size_t)(bm + ty * 8 + i) * GN + bn + tx * 4] = o;
    }

    __threadfence();
    __syncthreads();
    if (tid == 0) atomicAdd(&g_flag[bb][tb], 1);
}

// ---------------------------------------------------------------------------
// srnn helpers
// ---------------------------------------------------------------------------
__device__ __forceinline__ unsigned long long addx2(unsigned long long a,
                                                    unsigned long long b) {
    unsigned long long r;
    asm("add.rn.f32x2 %0, %1, %2;" : "=l"(r) : "l"(a), "l"(b));
    return r;
}
__device__ __forceinline__ float lo2(unsigned long long v) {
    return __int_as_float((int)(unsigned)(v & 0xffffffffull));
}
__device__ __forceinline__ float hi2(unsigned long long v) {
    return __int_as_float((int)(unsigned)(v >> 32));
}
__device__ __forceinline__ unsigned spread16(unsigned x) {
    x &= 0xffffu;
    x = (x | (x << 8)) & 0x00FF00FFu;
    x = (x | (x << 4)) & 0x0F0F0F0Fu;
    x = (x | (x << 2)) & 0x33333333u;
    x = (x | (x << 1)) & 0x55555555u;
    return x;
}

// 8 rows, 8B slice each, indices via one LDS.128
__device__ __forceinline__ void ld_chunk8(const float* __restrict__ wbase,
                                          const unsigned short* __restrict__ idx,
                                          int k, unsigned long long* buf) {
    uint4 iv = *(const uint4*)(idx + k);
    buf[0] = *(const unsigned long long*)(wbase + ((iv.x & 0xffffu) << 10));
    buf[1] = *(const unsigned long long*)(wbase + ((iv.x >> 16) << 10));
    buf[2] = *(const unsigned long long*)(wbase + ((iv.y & 0xffffu) << 10));
    buf[3] = *(const unsigned long long*)(wbase + ((iv.y >> 16) << 10));
    buf[4] = *(const unsigned long long*)(wbase + ((iv.z & 0xffffu) << 10));
    buf[5] = *(const unsigned long long*)(wbase + ((iv.z >> 16) << 10));
    buf[6] = *(const unsigned long long*)(wbase + ((iv.w & 0xffffu) << 10));
    buf[7] = *(const unsigned long long*)(wbase + ((iv.w >> 16) << 10));
}
__device__ __forceinline__ void acc_chunk8(const unsigned long long* buf,
                                           unsigned long long& a01) {
#pragma unroll
    for (int j = 0; j < 8; ++j) a01 = addx2(a01, buf[j]);
}
__device__ __forceinline__ void accum_rows8(const float* __restrict__ wbase,
                                            const unsigned short* __restrict__ idx,
                                            int n, unsigned long long& a01) {
    const int nc = n >> 4;
    if (nc == 0) return;
    unsigned long long A[8], Bf[8];
    ld_chunk8(wbase, idx, 0, A);
    ld_chunk8(wbase, idx, 8, Bf);
    int k = 16;
    for (int c = 1; c < nc; ++c) {
        acc_chunk8(A, a01);
        ld_chunk8(wbase, idx, k, A);
        acc_chunk8(Bf, a01);
        ld_chunk8(wbase, idx, k + 8, Bf);
        k += 16;
    }
    acc_chunk8(A, a01);
    acc_chunk8(Bf, a01);
}

// ---------------------------------------------------------------------------
// srnn body: rank rk in {0,1}, owns cols [rk*512, rk*512+512)
// ---------------------------------------------------------------------------
__device__ void srnn_body(int b, int rk,
                          const float* __restrict__ b_h1,
                          const float* __restrict__ b_12,
                          const float* __restrict__ b_h2,
                          const float* __restrict__ b_out,
                          float* __restrict__ out) {
    const int tid = threadIdx.x;
    const int lane = tid & 31;
    const int warp = tid >> 5;
    const int peer = rk ^ 1;

    __shared__ alignas(16) unsigned short idx1[H + 16];
    __shared__ alignas(16) unsigned short idx2[H + 16];
    __shared__ unsigned mwords[16];    // own 16 mask words
    __shared__ int cnt_s;
    __shared__ float4 red4[128];

    const int colbase = rk * HC;
    const int col = colbase + tid * 2;
    const float* wh1 = g_WT_h1 + col;
    const float* w12 = g_WT_12 + col;
    const float* wh2 = g_WT_h2 + col;

    float2 v1 = make_float2(0.f, 0.f);
    float2 v2 = make_float2(0.f, 0.f);

    const float2 bh1 = *(const float2*)(b_h1 + col);
    const float2 b12 = *(const float2*)(b_12 + col);
    const float2 bh2 = *(const float2*)(b_h2 + col);

    // readout: this CTA computes partials p = rk*2 + (tid>>6) for tid<128
    const int pr = tid >> 6;            // 0/1 within CTA
    const int o = tid & 63;
    const float* wout = g_WT_out + o * 4;
    float4 accp = make_float4(0.f, 0.f, 0.f, 0.f);
    float4 bo = make_float4(0.f, 0.f, 0.f, 0.f);
    const bool do_ro = tid < 128;
    if (rk == 0 && tid < 64) bo = *(const float4*)(b_out + o * 4);
    const int kstart = rk * 2 + pr;     // global partial index 0..3

    const float* Xb = g_Xa + (size_t)b * T * H;
    int n1 = 0, n2 = 0;

    for (int t = 0; t < T; ++t) {
        if ((t & 127) == 0) {
            const int tb = t >> 7;
            if (tid == 0) {
                while (atomicAdd(&g_flag[b][tb], 0) < NTILES) __nanosleep(100);
            }
            __syncthreads();
            __threadfence();
        }

        // ================= layer 1 =================
        float2 hx = *(const float2*)(Xb + t * H + col);
        unsigned long long r01 = 0ull;
        accum_rows8(wh1, idx1, n1, r01);
        float nx = (hx.x + lo2(r01)) + bh1.x;
        float ny = (hx.y + hi2(r01)) + bh1.y;
        v1.x = fmaf(BETA, v1.x, nx);
        v1.y = fmaf(BETA, v1.y, ny);
        bool s0 = v1.x >= THRESH;
        bool s1 = v1.y >= THRESH;
        if (s0) v1.x -= THRESH;
        if (s1) v1.y -= THRESH;
        {
            unsigned b0 = __ballot_sync(0xffffffffu, s0);
            unsigned b1 = __ballot_sync(0xffffffffu, s1);
            if (lane == 0) {
                unsigned w0 = spread16(b0) | (spread16(b1) << 1);
                unsigned w1 = spread16(b0 >> 16) | (spread16(b1 >> 16) << 1);
                mwords[warp * 2] = w0;
                mwords[warp * 2 + 1] = w1;
                g_masks[b][0][rk][warp * 2] = w0;
                g_masks[b][0][rk][warp * 2 + 1] = w1;
            }
        }
        __syncthreads();
        if (tid == 0) {
            __threadfence();
            atomicAdd(&g_xf[b][0][rk], 1);
            while (atomicAdd(&g_xf[b][0][peer], 0) < t + 1) __nanosleep(100);
            __threadfence();
        }
        __syncthreads();
        if (tid < 32) {   // full-H compaction, ascending cols
            unsigned m;
            if ((tid >> 4) == rk) m = mwords[tid & 15];
            else m = __ldcg(&g_masks[b][0][peer][tid & 15]);
            int p = __popc(m);
            int off = p;
#pragma unroll
            for (int s = 1; s < 32; s <<= 1) {
                int n = __shfl_up_sync(0xffffffffu, off, s);
                if (lane >= s) off += n;
            }
            int tot = __shfl_sync(0xffffffffu, off, 31);
            if (tid == 31) cnt_s = (tot + 15) & ~15;
            off -= p;
            const int base = tid * 32;
            while (m) {
                int bit = __ffs(m) - 1;
                m &= m - 1;
                idx1[off++] = (unsigned short)(base + bit);
            }
            int npad = ((tot + 15) & ~15) - tot;
            if (tid < npad) idx1[tot + tid] = (unsigned short)ZROW;
        }
        __syncthreads();
        n1 = cnt_s;

        // ================= layer 2 =================
        unsigned long long a01 = 0ull;
        accum_rows8(w12, idx1, n1, a01);
        unsigned long long c01 = 0ull;
        accum_rows8(wh2, idx2, n2, c01);
        __syncthreads();   // idx2 about to be overwritten
        float m0 = ((lo2(a01) + b12.x) + lo2(c01)) + bh2.x;
        float m1 = ((hi2(a01) + b12.y) + hi2(c01)) + bh2.y;
        v2.x = fmaf(BETA, v2.x, m0);
        v2.y = fmaf(BETA, v2.y, m1);
        s0 = v2.x >= THRESH;
        s1 = v2.y >= THRESH;
        if (s0) v2.x -= THRESH;
        if (s1) v2.y -= THRESH;
        {
            unsigned b0 = __ballot_sync(0xffffffffu, s0);
            unsigned b1 = __ballot_sync(0xffffffffu, s1);
            if (lane == 0) {
                unsigned w0 = spread16(b0) | (spread16(b1) << 1);
                unsigned w1 = spread16(b0 >> 16) | (spread16(b1 >> 16) << 1);
                mwords[warp * 2] = w0;
                mwords[warp * 2 + 1] = w1;
                g_masks[b][1][rk][warp * 2] = w0;
                g_masks[b][1][rk][warp * 2 + 1] = w1;
            }
        }
        __syncthreads();
        if (tid == 0) {
            __threadfence();
            atomicAdd(&g_xf[b][1][rk], 1);
            while (atomicAdd(&g_xf[b][1][peer], 0) < t + 1) __nanosleep(100);
            __threadfence();
        }
        __syncthreads();
        if (tid < 32) {
            unsigned m;
            if ((tid >> 4) == rk) m = mwords[tid & 15];
            else m = __ldcg(&g_masks[b][1][peer][tid & 15]);
            int p = __popc(m);
            int off = p;
#pragma unroll
            for (int s = 1; s < 32; s <<= 1) {
                int n = __shfl_up_sync(0xffffffffu, off, s);
                if (lane >= s) off += n;
            }
            int tot = __shfl_sync(0xffffffffu, off, 31);
            if (tid == 31) cnt_s = (tot + 15) & ~15;
            off -= p;
            const int base = tid * 32;
            while (m) {
                int bit = __ffs(m) - 1;
                m &= m - 1;
                idx2[off++] = (unsigned short)(base + bit);
            }
            int npad = ((tot + 15) & ~15) - tot;
            if (tid < npad) idx2[tot + tid] = (unsigned short)ZROW;
        }
        __syncthreads();
        n2 = cnt_s;

        // ================= readout partials (pads add +0) ==================
        if (do_ro) {
            float4 a = accp;
            if (rk == 0 && pr == 0) {
                a.x += bo.x;
                a.y += bo.y;
                a.z += bo.z;
                a.w += bo.w;
            }
            for (int k = kstart; k < n2; k += 16) {
                float4 w0 = *(const float4*)(wout + ((int)idx2[k] << 8));
                float4 w1 = *(const float4*)(wout + ((int)idx2[k + 4] << 8));
                float4 w2 = *(const float4*)(wout + ((int)idx2[k + 8] << 8));
                float4 w3 = *(const float4*)(wout + ((int)idx2[k + 12] << 8));
                a.x += w0.x; a.y += w0.y; a.z += w0.z; a.w += w0.w;
                a.x += w1.x; a.y += w1.y; a.z += w1.z; a.w += w1.w;
                a.x += w2.x; a.y += w2.y; a.z += w2.z; a.w += w2.w;
                a.x += w3.x; a.y += w3.y; a.z += w3.z; a.w += w3.w;
            }
            accp = a;
        }
    }

    // final combine: out = ((p0 + p1) + p2) + p3  (same order as R8)
    if (rk == 1) {
        if (do_ro) g_part[b][tid] = accp;
        __syncthreads();
        if (tid == 0) {
            __threadfence();
            atomicAdd(&g_rflag[b], 1);
        }
    } else {
        if (do_ro) red4[tid] = accp;
        if (tid == 0) {
            while (atomicAdd(&g_rflag[b], 0) < 1) __nanosleep(200);
            __threadfence();
        }
        __syncthreads();
        if (tid < 64) {
            float4 s = red4[tid];
            float4 p1 = red4[tid + 64];
            float4 p2 = __ldcg(&g_part[b][tid]);
            float4 p3 = __ldcg(&g_part[b][tid + 64]);
            s.x += p1.x; s.y += p1.y; s.z += p1.z; s.w += p1.w;
            s.x += p2.x; s.y += p2.y; s.z += p2.z; s.w += p2.w;
            s.x += p3.x; s.y += p3.y; s.z += p3.z; s.w += p3.w;
            *(float4*)&out[b * DOUT + tid * 4] = s;
        }
    }
}

// ---------------------------------------------------------------------------
__global__ __launch_bounds__(256) void fused_kernel(
    const float* __restrict__ x, const float* __restrict__ b_in,
    const float* __restrict__ b_h1, const float* __restrict__ b_12,
    const float* __restrict__ b_h2, const float* __restrict__ b_out,
    float* __restrict__ out) {
    if (blockIdx.x < 2 * B) {
        srnn_body(blockIdx.x & 63, blockIdx.x >> 6, b_h1, b_12, b_h2, b_out, out);
    } else {
        gemm_body(x, b_in, blockIdx.x - 2 * B);
    }
}

// ---------------------------------------------------------------------------
extern "C" void kernel_launch(void* const* d_in, const int* in_sizes, int n_in,
                              void* d_out, int out_size) {
    const float* x = (const float*)d_in[0];
    const float* W_in = (const float*)d_in[1];
    const float* b_in = (const float*)d_in[2];
    const float* b_h1 = (const float*)d_in[4];
    const float* b_12 = (const float*)d_in[6];
    const float* b_h2 = (const float*)d_in[8];
    const float* b_out = (const float*)d_in[10];
    float* out = (float*)d_out;

    prep_kernel<<<1024, 256>>>((const float*)d_in[1], (const float*)d_in[3],
                               (const float*)d_in[5], (const float*)d_in[7],
                               (const float*)d_in[9]);
    const int total_tiles = (B * T / BMT) * NTILES;   // 4096
    fused_kernel<<<2 * B + total_tiles, 256>>>(x, b_in, b_h1, b_12, b_h2, b_out,
                                               out);
    (void)W_in;
}